// round 15
// baseline (speedup 1.0000x reference)
#include <cuda_runtime.h>
#include <cuda_bf16.h>
#include <math.h>
#include <stdint.h>

#define EPS_C 0.001f
#define NITER_C 10

// -------- scratch (device globals; no allocation allowed) --------
__device__ float    g_H[3072 * 3072];
__device__ float    g_E[1024 * 1024];
__device__ uint16_t g_XThi[3072 * 3072];
__device__ uint16_t g_XTlo[3072 * 3072];
__device__ float    g_pre[1024];
__device__ float    g_eps[1024];
__device__ float    g_exi[1024];
__device__ float    g_x[2][1024];
__device__ float    g_d[2][1024];
__device__ unsigned int g_bar_count = 0;
__device__ unsigned int g_bar_gen = 0;

// =====================================================================
// PTX helpers (arch-agnostic: cp.async sm_80+, ldmatrix sm_75+, mma sm_80+)
// =====================================================================
__device__ __forceinline__ uint32_t smem_u32(const void* p) {
    return (uint32_t)__cvta_generic_to_shared(p);
}
__device__ __forceinline__ void cp16(uint32_t dst, const void* src) {
    asm volatile("cp.async.cg.shared.global [%0], [%1], 16;" :: "r"(dst), "l"(src));
}
__device__ __forceinline__ void cp_commit() {
    asm volatile("cp.async.commit_group;");
}
template <int N>
__device__ __forceinline__ void cp_wait() {
    asm volatile("cp.async.wait_group %0;" :: "n"(N) : "memory");
}
#define LDSM_X4(R0, R1, R2, R3, ADDR)                                          \
    asm volatile("ldmatrix.sync.aligned.m8n8.x4.shared.b16 {%0,%1,%2,%3}, [%4];" \
                 : "=r"(R0), "=r"(R1), "=r"(R2), "=r"(R3) : "r"(ADDR))
#define MMA_BF16(C0, C1, C2, C3, A0, A1, A2, A3, B0, B1)                       \
    asm volatile("mma.sync.aligned.m16n8k16.row.col.f32.bf16.bf16.f32 "        \
                 "{%0,%1,%2,%3}, {%4,%5,%6,%7}, {%8,%9}, {%0,%1,%2,%3};"       \
                 : "+f"(C0), "+f"(C1), "+f"(C2), "+f"(C3)                      \
                 : "r"(A0), "r"(A1), "r"(A2), "r"(A3), "r"(B0), "r"(B1))

// =====================================================================
// software grid barrier (all CTAs must be co-resident)
// =====================================================================
__device__ __forceinline__ void grid_bar() {
    __syncthreads();
    if (threadIdx.x == 0) {
        __threadfence();
        unsigned int gen = ((volatile unsigned int*)&g_bar_gen)[0];
        if (atomicAdd(&g_bar_count, 1u) == gridDim.x - 1) {
            g_bar_count = 0;
            __threadfence();
            ((volatile unsigned int*)&g_bar_gen)[0] = gen + 1;
        } else {
            while (((volatile unsigned int*)&g_bar_gen)[0] == gen) {}
            __threadfence();
        }
    }
    __syncthreads();
}

// =====================================================================
// Transpose + bf16 split conversion: XT[n][k] = X[k][n] -> (hi, lo)
// =====================================================================
__global__ void conv_transpose(const float* __restrict__ X) {
    __shared__ float s[32][33];
    int k0 = blockIdx.x * 32;
    int n0 = blockIdx.y * 32;
    int tx = threadIdx.x;
    int ty = threadIdx.y;
#pragma unroll
    for (int i = 0; i < 32; i += 8)
        s[ty + i][tx] = X[(size_t)(k0 + ty + i) * 3072 + n0 + tx];
    __syncthreads();
#pragma unroll
    for (int i = 0; i < 32; i += 8) {
        int n = n0 + ty + i;
        int k = k0 + tx;
        float v = s[tx][ty + i];
        __nv_bfloat16 h = __float2bfloat16(v);
        float hv = __bfloat162float(h);
        __nv_bfloat16 l = __float2bfloat16(v - hv);
        size_t o = (size_t)n * 3072 + k;
        g_XThi[o] = __bfloat16_as_ushort(h);
        g_XTlo[o] = __bfloat16_as_ushort(l);
    }
}

// =====================================================================
// mma.sync SYRK (bf16-split): 192x192 CTA tiles, 136 CTAs = 1 wave.
// =====================================================================
#define ROW_BYTES   144
#define HALF_BYTES  55296
#define STAGE_BYTES 110592

__global__ __launch_bounds__(256, 1) void syrk_mma() {
    extern __shared__ __align__(16) char smem[];

    int b = blockIdx.x;
    int tr = (int)((sqrtf(8.0f * (float)b + 1.0f) - 1.0f) * 0.5f);
    while ((tr + 1) * (tr + 2) / 2 <= b) tr++;
    while (tr * (tr + 1) / 2 > b) tr--;
    int tc = b - tr * (tr + 1) / 2;
    int i0 = tr * 192;
    int j0 = tc * 192;

    int t = threadIdx.x;
    int lane = t & 31;
    int wid = t >> 5;
    int warp_m = wid >> 1;
    int warp_n = wid & 1;

    uint32_t sbase = smem_u32(smem);

    float acc[3][12][4] = {};

    int lrow = lane & 15;
    int lcol = (lane >> 4) * 8;

    int lr8 = t >> 3;
    int lkp = t & 7;

    auto issue_chunk = [&](int c, uint32_t stage_base) {
        int k0 = c * 64;
#pragma unroll
        for (int it = 0; it < 6; it++) {
            int row = lr8 + it * 32;
            uint32_t dst = stage_base + (uint32_t)(row * ROW_BYTES + lkp * 16);
            size_t go = (size_t)(i0 + row) * 3072 + k0 + lkp * 8;
            cp16(dst, g_XThi + go);
            cp16(dst + HALF_BYTES, g_XTlo + go);
        }
#pragma unroll
        for (int it = 0; it < 6; it++) {
            int row = lr8 + it * 32;
            uint32_t dst = stage_base + (uint32_t)((192 + row) * ROW_BYTES + lkp * 16);
            size_t go = (size_t)(j0 + row) * 3072 + k0 + lkp * 8;
            cp16(dst, g_XThi + go);
            cp16(dst + HALF_BYTES, g_XTlo + go);
        }
        cp_commit();
    };

    issue_chunk(0, sbase);

    for (int c = 0; c < 48; c++) {
        uint32_t cur = sbase + (uint32_t)((c & 1) * STAGE_BYTES);
        if (c + 1 < 48) {
            issue_chunk(c + 1, sbase + (uint32_t)(((c + 1) & 1) * STAGE_BYTES));
            cp_wait<1>();
        } else {
            cp_wait<0>();
        }
        __syncthreads();

        uint32_t sHi = cur;
        uint32_t sLo = cur + HALF_BYTES;

#pragma unroll
        for (int kk = 0; kk < 4; kk++) {
            int kcol = kk * 16 + lcol;
            uint32_t bh[6][4], bl[6][4];
#pragma unroll
            for (int np = 0; np < 6; np++) {
                uint32_t off = (uint32_t)((192 + warp_n * 96 + np * 16 + lrow) * ROW_BYTES + kcol * 2);
                LDSM_X4(bh[np][0], bh[np][1], bh[np][2], bh[np][3], sHi + off);
                LDSM_X4(bl[np][0], bl[np][1], bl[np][2], bl[np][3], sLo + off);
            }
#pragma unroll
            for (int mt = 0; mt < 3; mt++) {
                uint32_t offA = (uint32_t)((warp_m * 48 + mt * 16 + lrow) * ROW_BYTES + kcol * 2);
                uint32_t ah[4], al[4];
                LDSM_X4(ah[0], ah[1], ah[2], ah[3], sHi + offA);
                LDSM_X4(al[0], al[1], al[2], al[3], sLo + offA);
#pragma unroll
                for (int nt = 0; nt < 12; nt++) {
                    float* a4 = acc[mt][nt];
                    MMA_BF16(a4[0], a4[1], a4[2], a4[3],
                             ah[0], ah[1], ah[2], ah[3],
                             bh[nt >> 1][nt & 1], bh[nt >> 1][2 + (nt & 1)]);
                }
#pragma unroll
                for (int nt = 0; nt < 12; nt++) {
                    float* a4 = acc[mt][nt];
                    MMA_BF16(a4[0], a4[1], a4[2], a4[3],
                             ah[0], ah[1], ah[2], ah[3],
                             bl[nt >> 1][nt & 1], bl[nt >> 1][2 + (nt & 1)]);
                }
#pragma unroll
                for (int nt = 0; nt < 12; nt++) {
                    float* a4 = acc[mt][nt];
                    MMA_BF16(a4[0], a4[1], a4[2], a4[3],
                             al[0], al[1], al[2], al[3],
                             bh[nt >> 1][nt & 1], bh[nt >> 1][2 + (nt & 1)]);
                }
            }
        }
        __syncthreads();
    }

    int gid = lane >> 2;
    int tig = lane & 3;
#pragma unroll
    for (int mt = 0; mt < 3; mt++) {
        int gi = i0 + warp_m * 48 + mt * 16 + gid;
#pragma unroll
        for (int nt = 0; nt < 12; nt++) {
            int gj = j0 + warp_n * 96 + nt * 8 + tig * 2;
            float v0 = acc[mt][nt][0], v1 = acc[mt][nt][1];
            float v2 = acc[mt][nt][2], v3 = acc[mt][nt][3];
            if (tr == tc) {
                if (gi == gj) v0 += EPS_C;
                if (gi == gj + 1) v1 += EPS_C;
                if (gi + 8 == gj) v2 += EPS_C;
                if (gi + 8 == gj + 1) v3 += EPS_C;
            }
            *(float2*)(g_H + (size_t)gi * 3072 + gj) = make_float2(v0, v1);
            *(float2*)(g_H + (size_t)(gi + 8) * 3072 + gj) = make_float2(v2, v3);
        }
    }
}

// =====================================================================
// warp dot helper
// =====================================================================
template <int N>
__device__ __forceinline__ float warp_dot(const float* __restrict__ a,
                                          const float* __restrict__ v, int lane) {
    float s = 0.f;
#pragma unroll
    for (int c = 0; c < N / 4; c += 32) {
        float4 av = *(const float4*)(a + (size_t)(c + lane) * 4);
        float4 vv = *(const float4*)(v + (size_t)(c + lane) * 4);
        s = fmaf(av.x, vv.x, s);
        s = fmaf(av.y, vv.y, s);
        s = fmaf(av.z, vv.z, s);
        s = fmaf(av.w, vv.w, s);
    }
#pragma unroll
    for (int off = 16; off; off >>= 1) s += __shfl_xor_sync(0xffffffffu, s, off);
    return s;
}

// =====================================================================
// FUSED: build_E (blocks 0..527) + pre (blocks 528..783)
// =====================================================================
__global__ __launch_bounds__(256) void be_pre_kernel(const float* __restrict__ Y,
                                                     const float* __restrict__ xi,
                                                     const float* __restrict__ w,
                                                     const float* __restrict__ D12) {
    __shared__ float sH[32][33], sY[32][33], sYT[32][33], sM[32][33];

    if (blockIdx.x < 528) {
        int b = blockIdx.x;
        int bi = (int)((sqrtf(8.0f * (float)b + 1.0f) - 1.0f) * 0.5f);
        while ((bi + 1) * (bi + 2) / 2 <= b) bi++;
        while (bi * (bi + 1) / 2 > b) bi--;
        int bj = b - bi * (bi + 1) / 2;
        int i0 = bi * 32, j0 = bj * 32;

        int tx = threadIdx.x & 31;
        int ty = threadIdx.x >> 5;

#pragma unroll
        for (int r = ty; r < 32; r += 8) {
            sH[r][tx] = 0.5f * (g_H[(size_t)(i0 + r) * 3072 + j0 + tx] +
                                g_H[(size_t)(2048 + i0 + r) * 3072 + 2048 + j0 + tx]);
            sY[r][tx]  = Y[(size_t)(i0 + r) * 1024 + j0 + tx];
            sYT[r][tx] = Y[(size_t)(j0 + r) * 1024 + i0 + tx];
        }
        __syncthreads();
#pragma unroll
        for (int r = ty; r < 32; r += 8) {
            float hs = sH[r][tx];
            float yd = 0.5f * (sY[r][tx] - sYT[tx][r]);
            g_E[(size_t)(i0 + r) * 1024 + j0 + tx] = hs + yd;
            sM[tx][r] = hs - yd;
        }
        __syncthreads();
#pragma unroll
        for (int r = ty; r < 32; r += 8)
            g_E[(size_t)(j0 + r) * 1024 + i0 + tx] = sM[r][tx];
    } else {
        int blk = blockIdx.x - 528;
        int t = threadIdx.x;
        int wid = t >> 5, lane = t & 31;
        int rl = wid >> 1, half = wid & 1;
        int row = blk * 4 + rl;

        const float* hrow = g_H + (size_t)(1024 + row) * 3072;
        float s = -warp_dot<512>(hrow + half * 512, xi + half * 512, lane);
        s += warp_dot<256>(D12 + (size_t)row * 512 + half * 256, w + half * 256, lane);
        if (lane == 0) sH[0][wid] = s;
        __syncthreads();
        if (t < 4) g_pre[blk * 4 + t] = sH[0][2 * t] + sH[0][2 * t + 1];
    }
}

// =====================================================================
// HW tanh (MUFU.TANH, sm_75+)
// =====================================================================
__device__ __forceinline__ float tanh_mufu(float x) {
    float y;
    asm("tanh.approx.f32 %0, %1;" : "=f"(y) : "f"(x));
    return y;
}

// =====================================================================
// Sequential tanh recurrence -- SOFTWARE-PIPELINED:
// while warp 0 runs block b's 32-step serial chain, warps 1..31 compute
// block b+1's long prefix matvec (cols [0, r0)) and prefetch its scaled
// diagonal (sDs) and sub-diagonal (sDn) blocks. The only serial coupling
// across blocks is the 32-wide "new" dot, folded into the serial start.
// =====================================================================
__global__ __launch_bounds__(1024) void scan_kernel() {
    __shared__ float seps[1024];
    __shared__ float sPre[1024];
    __shared__ float sPartial[2][32];
    __shared__ float sDs[2][32][33];
    __shared__ float sDn[2][32][33];
    __shared__ float sInv[2][32];

    int t = threadIdx.x;
    int w = t >> 5;
    int lane = t & 31;

    sPre[t] = g_pre[t];

    // prologue: block 0 diag data (warp w -> row w of block 0)
    {
        const float* hrow = g_H + (size_t)(1024 + w) * 3072 + 1024;
        float diag = hrow[w];
        float inv = 1.0f / diag;
        float hds = (lane < w) ? hrow[lane] : 0.f;
        sDs[0][w][lane] = -hds * inv;
        sDn[0][w][lane] = 0.f;
        if (lane == 0) { sInv[0][w] = inv; sPartial[0][w] = 0.f; }
    }
    __syncthreads();

    for (int b = 0; b < 32; b++) {
        int r0 = b * 32;
        int cur = b & 1, nxt = cur ^ 1;

        if (w == 0) {
            // ---- serial phase for block b ----
            float ds[32];
#pragma unroll
            for (int j = 0; j < 32; j++) ds[j] = sDs[cur][lane][j];
            float acc = (sPre[r0 + lane] + sPartial[cur][lane]) * sInv[cur][lane];
            if (b > 0) {
#pragma unroll
                for (int j = 0; j < 32; j++)
                    acc = fmaf(sDn[cur][lane][j], seps[r0 - 32 + j], acc);
            }
            float tv = 0.f;
#pragma unroll
            for (int j = 0; j < 32; j++) {
                tv = tanh_mufu(acc);
                float e = __shfl_sync(0xffffffffu, tv, j);
                acc = fmaf(ds[j], e, acc);
            }
            seps[r0 + lane] = tv;
        } else if (b < 31) {
            // ---- prefetch block b+1 (rows 0..30 by warps 1..31; warp 31 also row 31) ----
            int nr0 = r0 + 32;
            int nrows = (w == 31) ? 2 : 1;
            for (int q = 0; q < nrows; q++) {
                int row = (q == 0) ? (w - 1) : 31;
                const float* hrow = g_H + (size_t)(1024 + nr0 + row) * 3072 + 1024;
                float diag = hrow[nr0 + row];
                float inv = 1.0f / diag;
                float hds = (lane < row) ? hrow[nr0 + lane] : 0.f;
                float hdn = hrow[r0 + lane];
                float s = 0.f;
                for (int c = lane * 4; c < r0; c += 128) {
                    float4 a = *(const float4*)(hrow + c);
                    float4 e = *(const float4*)(seps + c);
                    s -= a.x * e.x + a.y * e.y + a.z * e.z + a.w * e.w;
                }
#pragma unroll
                for (int off = 16; off; off >>= 1) s += __shfl_xor_sync(0xffffffffu, s, off);
                sDs[nxt][row][lane] = -hds * inv;
                sDn[nxt][row][lane] = -hdn * inv;
                if (lane == 0) { sInv[nxt][row] = inv; sPartial[nxt][row] = s; }
            }
        }
        __syncthreads();
    }
    g_eps[t] = seps[t];
}

// =====================================================================
// FUSED: u (blocks 0..127) + exi (+cheb init) (blocks 128..383)
// =====================================================================
__global__ __launch_bounds__(256) void u_exi_kernel(const float* __restrict__ xi,
                                                    const float* __restrict__ w,
                                                    const float* __restrict__ C2,
                                                    const float* __restrict__ D21,
                                                    const float* __restrict__ D22,
                                                    const float* __restrict__ B2,
                                                    float inv_theta,
                                                    float* __restrict__ out) {
    __shared__ float part[8];
    int t = threadIdx.x;
    int wid = t >> 5, lane = t & 31;
    int rl = wid >> 1, half = wid & 1;

    if (blockIdx.x < 128) {
        int row = blockIdx.x * 4 + rl;
        float s = warp_dot<512>(C2 + (size_t)row * 1024 + half * 512, xi + half * 512, lane);
        s += warp_dot<512>(D21 + (size_t)row * 1024 + half * 512, g_eps + half * 512, lane);
        s += warp_dot<256>(D22 + (size_t)row * 512 + half * 256, w + half * 256, lane);
        if (lane == 0) part[wid] = s;
        __syncthreads();
        if (t < 4) out[blockIdx.x * 4 + t] = part[2 * t] + part[2 * t + 1];
    } else {
        int blk = blockIdx.x - 128;
        int row = blk * 4 + rl;
        const float* hrow = g_H + (size_t)(2048 + row) * 3072;
        float s = warp_dot<512>(hrow + half * 512, xi + half * 512, lane);
        s += warp_dot<512>(hrow + 1024 + half * 512, g_eps + half * 512, lane);
        s += warp_dot<256>(B2 + (size_t)row * 512 + half * 256, w + half * 256, lane);
        if (lane == 0) part[wid] = s;
        __syncthreads();
        if (t < 4) {
            int r = blk * 4 + t;
            float v = part[2 * t] + part[2 * t + 1];
            g_exi[r] = v;
            float x0 = v * inv_theta;
            g_x[0][r] = x0;
            g_d[0][r] = x0;
        }
    }
}

// =====================================================================
// PERSISTENT Chebyshev: all NITER_C iterations in one kernel.
// =====================================================================
__global__ __launch_bounds__(256) void cheb_persist(float* __restrict__ out,
                                                    float theta_f, float delta_f) {
    __shared__ float part[8];
    int t = threadIdx.x;
    int wid = t >> 5, lane = t & 31;
    int rl = wid >> 1, half = wid & 1;
    int row = blockIdx.x * 4 + rl;

    double theta = (double)theta_f, delta = (double)delta_f;
    double sigma = theta / delta;
    double rho_prev = 1.0 / sigma;
    int sel = 0;

    for (int k = 0; k < NITER_C; k++) {
        double rho = 1.0 / (2.0 * sigma - rho_prev);
        float c1 = (float)(rho * rho_prev);
        float c2 = (float)(2.0 * rho / delta);

        const float* xin = g_x[sel];
        float s = warp_dot<512>(g_E + (size_t)row * 1024 + half * 512, xin + half * 512, lane);
        if (lane == 0) part[wid] = s;
        __syncthreads();
        if (t < 4) {
            int r = blockIdx.x * 4 + t;
            float dot = part[2 * t] + part[2 * t + 1];
            float rres = g_exi[r] - dot;
            float dn = fmaf(c1, g_d[sel][r], c2 * rres);
            float xn = xin[r] + dn;
            g_x[sel ^ 1][r] = xn;
            g_d[sel ^ 1][r] = dn;
            if (k == NITER_C - 1) out[r] = xn;
        }
        grid_bar();
        rho_prev = rho;
        sel ^= 1;
    }
}

// =====================================================================
// host launcher
// =====================================================================
extern "C" void kernel_launch(void* const* d_in, const int* in_sizes, int n_in,
                              void* d_out, int out_size) {
    const float* w   = (const float*)d_in[1];
    const float* xi  = (const float*)d_in[2];
    const float* X   = (const float*)d_in[3];
    const float* Y   = (const float*)d_in[4];
    const float* B2  = (const float*)d_in[5];
    const float* C2  = (const float*)d_in[6];
    const float* D21 = (const float*)d_in[7];
    const float* D22 = (const float*)d_in[8];
    const float* D12 = (const float*)d_in[9];
    float* out = (float*)d_out;

    const double a_bnd = 9.5, b_bnd = 64.0;
    const double theta = 0.5 * (a_bnd + b_bnd);
    const double delta = 0.5 * (b_bnd - a_bnd);

    conv_transpose<<<dim3(96, 96), dim3(32, 8)>>>(X);

    static int smem_set = 0;
    if (!smem_set) {
        cudaFuncSetAttribute(syrk_mma, cudaFuncAttributeMaxDynamicSharedMemorySize, 2 * STAGE_BYTES);
        smem_set = 1;
    }
    syrk_mma<<<136, 256, 2 * STAGE_BYTES>>>();

    be_pre_kernel<<<784, 256>>>(Y, xi, w, D12);
    scan_kernel<<<1, 1024>>>();
    u_exi_kernel<<<384, 256>>>(xi, w, C2, D21, D22, B2, (float)(1.0 / theta), out);
    cheb_persist<<<256, 256>>>(out + 512, (float)theta, (float)delta);
}

// round 16
// speedup vs baseline: 1.1098x; 1.1098x over previous
#include <cuda_runtime.h>
#include <cuda_bf16.h>
#include <math.h>
#include <stdint.h>

#define EPS_C 0.001f
#define NITER_C 10

// -------- scratch (device globals; no allocation allowed) --------
__device__ float    g_H[3072 * 3072];
__device__ float    g_E[1024 * 1024];
__device__ uint16_t g_XThi[3072 * 3072];
__device__ uint16_t g_XTlo[3072 * 3072];
__device__ float    g_pre[1024];
__device__ float    g_eps[1024];
__device__ float    g_exi[1024];
__device__ float    g_x[2][1024];
__device__ float    g_d[2][1024];
__device__ unsigned int g_bar_count = 0;
__device__ unsigned int g_bar_gen = 0;

// =====================================================================
// PTX helpers (arch-agnostic: cp.async sm_80+, ldmatrix sm_75+, mma sm_80+)
// =====================================================================
__device__ __forceinline__ uint32_t smem_u32(const void* p) {
    return (uint32_t)__cvta_generic_to_shared(p);
}
__device__ __forceinline__ void cp16(uint32_t dst, const void* src) {
    asm volatile("cp.async.cg.shared.global [%0], [%1], 16;" :: "r"(dst), "l"(src));
}
__device__ __forceinline__ void cp_commit() {
    asm volatile("cp.async.commit_group;");
}
template <int N>
__device__ __forceinline__ void cp_wait() {
    asm volatile("cp.async.wait_group %0;" :: "n"(N) : "memory");
}
#define LDSM_X4(R0, R1, R2, R3, ADDR)                                          \
    asm volatile("ldmatrix.sync.aligned.m8n8.x4.shared.b16 {%0,%1,%2,%3}, [%4];" \
                 : "=r"(R0), "=r"(R1), "=r"(R2), "=r"(R3) : "r"(ADDR))
#define MMA_BF16(C0, C1, C2, C3, A0, A1, A2, A3, B0, B1)                       \
    asm volatile("mma.sync.aligned.m16n8k16.row.col.f32.bf16.bf16.f32 "        \
                 "{%0,%1,%2,%3}, {%4,%5,%6,%7}, {%8,%9}, {%0,%1,%2,%3};"       \
                 : "+f"(C0), "+f"(C1), "+f"(C2), "+f"(C3)                      \
                 : "r"(A0), "r"(A1), "r"(A2), "r"(A3), "r"(B0), "r"(B1))

// =====================================================================
// software grid barrier (all CTAs must be co-resident)
// =====================================================================
__device__ __forceinline__ void grid_bar() {
    __syncthreads();
    if (threadIdx.x == 0) {
        __threadfence();
        unsigned int gen = ((volatile unsigned int*)&g_bar_gen)[0];
        if (atomicAdd(&g_bar_count, 1u) == gridDim.x - 1) {
            g_bar_count = 0;
            __threadfence();
            ((volatile unsigned int*)&g_bar_gen)[0] = gen + 1;
        } else {
            while (((volatile unsigned int*)&g_bar_gen)[0] == gen) {}
            __threadfence();
        }
    }
    __syncthreads();
}

// =====================================================================
// Transpose + bf16 split conversion: XT[n][k] = X[k][n] -> (hi, lo)
// =====================================================================
__global__ void conv_transpose(const float* __restrict__ X) {
    __shared__ float s[32][33];
    int k0 = blockIdx.x * 32;
    int n0 = blockIdx.y * 32;
    int tx = threadIdx.x;
    int ty = threadIdx.y;
#pragma unroll
    for (int i = 0; i < 32; i += 8)
        s[ty + i][tx] = X[(size_t)(k0 + ty + i) * 3072 + n0 + tx];
    __syncthreads();
#pragma unroll
    for (int i = 0; i < 32; i += 8) {
        int n = n0 + ty + i;
        int k = k0 + tx;
        float v = s[tx][ty + i];
        __nv_bfloat16 h = __float2bfloat16(v);
        float hv = __bfloat162float(h);
        __nv_bfloat16 l = __float2bfloat16(v - hv);
        size_t o = (size_t)n * 3072 + k;
        g_XThi[o] = __bfloat16_as_ushort(h);
        g_XTlo[o] = __bfloat16_as_ushort(l);
    }
}

// =====================================================================
// mma.sync SYRK (bf16-split): 192x192 CTA tiles, 136 CTAs = 1 wave.
// =====================================================================
#define ROW_BYTES   144
#define HALF_BYTES  55296
#define STAGE_BYTES 110592

__global__ __launch_bounds__(256, 1) void syrk_mma() {
    extern __shared__ __align__(16) char smem[];

    int b = blockIdx.x;
    int tr = (int)((sqrtf(8.0f * (float)b + 1.0f) - 1.0f) * 0.5f);
    while ((tr + 1) * (tr + 2) / 2 <= b) tr++;
    while (tr * (tr + 1) / 2 > b) tr--;
    int tc = b - tr * (tr + 1) / 2;
    int i0 = tr * 192;
    int j0 = tc * 192;

    int t = threadIdx.x;
    int lane = t & 31;
    int wid = t >> 5;
    int warp_m = wid >> 1;
    int warp_n = wid & 1;

    uint32_t sbase = smem_u32(smem);

    float acc[3][12][4] = {};

    int lrow = lane & 15;
    int lcol = (lane >> 4) * 8;

    int lr8 = t >> 3;
    int lkp = t & 7;

    auto issue_chunk = [&](int c, uint32_t stage_base) {
        int k0 = c * 64;
#pragma unroll
        for (int it = 0; it < 6; it++) {
            int row = lr8 + it * 32;
            uint32_t dst = stage_base + (uint32_t)(row * ROW_BYTES + lkp * 16);
            size_t go = (size_t)(i0 + row) * 3072 + k0 + lkp * 8;
            cp16(dst, g_XThi + go);
            cp16(dst + HALF_BYTES, g_XTlo + go);
        }
#pragma unroll
        for (int it = 0; it < 6; it++) {
            int row = lr8 + it * 32;
            uint32_t dst = stage_base + (uint32_t)((192 + row) * ROW_BYTES + lkp * 16);
            size_t go = (size_t)(j0 + row) * 3072 + k0 + lkp * 8;
            cp16(dst, g_XThi + go);
            cp16(dst + HALF_BYTES, g_XTlo + go);
        }
        cp_commit();
    };

    issue_chunk(0, sbase);

    for (int c = 0; c < 48; c++) {
        uint32_t cur = sbase + (uint32_t)((c & 1) * STAGE_BYTES);
        if (c + 1 < 48) {
            issue_chunk(c + 1, sbase + (uint32_t)(((c + 1) & 1) * STAGE_BYTES));
            cp_wait<1>();
        } else {
            cp_wait<0>();
        }
        __syncthreads();

        uint32_t sHi = cur;
        uint32_t sLo = cur + HALF_BYTES;

#pragma unroll
        for (int kk = 0; kk < 4; kk++) {
            int kcol = kk * 16 + lcol;
            uint32_t bh[6][4], bl[6][4];
#pragma unroll
            for (int np = 0; np < 6; np++) {
                uint32_t off = (uint32_t)((192 + warp_n * 96 + np * 16 + lrow) * ROW_BYTES + kcol * 2);
                LDSM_X4(bh[np][0], bh[np][1], bh[np][2], bh[np][3], sHi + off);
                LDSM_X4(bl[np][0], bl[np][1], bl[np][2], bl[np][3], sLo + off);
            }
#pragma unroll
            for (int mt = 0; mt < 3; mt++) {
                uint32_t offA = (uint32_t)((warp_m * 48 + mt * 16 + lrow) * ROW_BYTES + kcol * 2);
                uint32_t ah[4], al[4];
                LDSM_X4(ah[0], ah[1], ah[2], ah[3], sHi + offA);
                LDSM_X4(al[0], al[1], al[2], al[3], sLo + offA);
#pragma unroll
                for (int nt = 0; nt < 12; nt++) {
                    float* a4 = acc[mt][nt];
                    MMA_BF16(a4[0], a4[1], a4[2], a4[3],
                             ah[0], ah[1], ah[2], ah[3],
                             bh[nt >> 1][nt & 1], bh[nt >> 1][2 + (nt & 1)]);
                }
#pragma unroll
                for (int nt = 0; nt < 12; nt++) {
                    float* a4 = acc[mt][nt];
                    MMA_BF16(a4[0], a4[1], a4[2], a4[3],
                             ah[0], ah[1], ah[2], ah[3],
                             bl[nt >> 1][nt & 1], bl[nt >> 1][2 + (nt & 1)]);
                }
#pragma unroll
                for (int nt = 0; nt < 12; nt++) {
                    float* a4 = acc[mt][nt];
                    MMA_BF16(a4[0], a4[1], a4[2], a4[3],
                             al[0], al[1], al[2], al[3],
                             bh[nt >> 1][nt & 1], bh[nt >> 1][2 + (nt & 1)]);
                }
            }
        }
        __syncthreads();
    }

    int gid = lane >> 2;
    int tig = lane & 3;
#pragma unroll
    for (int mt = 0; mt < 3; mt++) {
        int gi = i0 + warp_m * 48 + mt * 16 + gid;
#pragma unroll
        for (int nt = 0; nt < 12; nt++) {
            int gj = j0 + warp_n * 96 + nt * 8 + tig * 2;
            float v0 = acc[mt][nt][0], v1 = acc[mt][nt][1];
            float v2 = acc[mt][nt][2], v3 = acc[mt][nt][3];
            if (tr == tc) {
                if (gi == gj) v0 += EPS_C;
                if (gi == gj + 1) v1 += EPS_C;
                if (gi + 8 == gj) v2 += EPS_C;
                if (gi + 8 == gj + 1) v3 += EPS_C;
            }
            *(float2*)(g_H + (size_t)gi * 3072 + gj) = make_float2(v0, v1);
            *(float2*)(g_H + (size_t)(gi + 8) * 3072 + gj) = make_float2(v2, v3);
        }
    }
}

// =====================================================================
// warp dot helper
// =====================================================================
template <int N>
__device__ __forceinline__ float warp_dot(const float* __restrict__ a,
                                          const float* __restrict__ v, int lane) {
    float s = 0.f;
#pragma unroll
    for (int c = 0; c < N / 4; c += 32) {
        float4 av = *(const float4*)(a + (size_t)(c + lane) * 4);
        float4 vv = *(const float4*)(v + (size_t)(c + lane) * 4);
        s = fmaf(av.x, vv.x, s);
        s = fmaf(av.y, vv.y, s);
        s = fmaf(av.z, vv.z, s);
        s = fmaf(av.w, vv.w, s);
    }
#pragma unroll
    for (int off = 16; off; off >>= 1) s += __shfl_xor_sync(0xffffffffu, s, off);
    return s;
}

// =====================================================================
// FUSED: build_E (blocks 0..527) + pre (blocks 528..783)
// =====================================================================
__global__ __launch_bounds__(256) void be_pre_kernel(const float* __restrict__ Y,
                                                     const float* __restrict__ xi,
                                                     const float* __restrict__ w,
                                                     const float* __restrict__ D12) {
    __shared__ float sH[32][33], sY[32][33], sYT[32][33], sM[32][33];

    if (blockIdx.x < 528) {
        int b = blockIdx.x;
        int bi = (int)((sqrtf(8.0f * (float)b + 1.0f) - 1.0f) * 0.5f);
        while ((bi + 1) * (bi + 2) / 2 <= b) bi++;
        while (bi * (bi + 1) / 2 > b) bi--;
        int bj = b - bi * (bi + 1) / 2;
        int i0 = bi * 32, j0 = bj * 32;

        int tx = threadIdx.x & 31;
        int ty = threadIdx.x >> 5;

#pragma unroll
        for (int r = ty; r < 32; r += 8) {
            sH[r][tx] = 0.5f * (g_H[(size_t)(i0 + r) * 3072 + j0 + tx] +
                                g_H[(size_t)(2048 + i0 + r) * 3072 + 2048 + j0 + tx]);
            sY[r][tx]  = Y[(size_t)(i0 + r) * 1024 + j0 + tx];
            sYT[r][tx] = Y[(size_t)(j0 + r) * 1024 + i0 + tx];
        }
        __syncthreads();
#pragma unroll
        for (int r = ty; r < 32; r += 8) {
            float hs = sH[r][tx];
            float yd = 0.5f * (sY[r][tx] - sYT[tx][r]);
            g_E[(size_t)(i0 + r) * 1024 + j0 + tx] = hs + yd;
            sM[tx][r] = hs - yd;
        }
        __syncthreads();
#pragma unroll
        for (int r = ty; r < 32; r += 8)
            g_E[(size_t)(j0 + r) * 1024 + i0 + tx] = sM[r][tx];
    } else {
        int blk = blockIdx.x - 528;
        int t = threadIdx.x;
        int wid = t >> 5, lane = t & 31;
        int rl = wid >> 1, half = wid & 1;
        int row = blk * 4 + rl;

        const float* hrow = g_H + (size_t)(1024 + row) * 3072;
        float s = -warp_dot<512>(hrow + half * 512, xi + half * 512, lane);
        s += warp_dot<256>(D12 + (size_t)row * 512 + half * 256, w + half * 256, lane);
        if (lane == 0) sH[0][wid] = s;
        __syncthreads();
        if (t < 4) g_pre[blk * 4 + t] = sH[0][2 * t] + sH[0][2 * t + 1];
    }
}

// =====================================================================
// HW tanh (MUFU.TANH, sm_75+) -- accuracy validated in R15 (rel_err
// unchanged at 2.5298e-4)
// =====================================================================
__device__ __forceinline__ float tanh_mufu(float x) {
    float y;
    asm("tanh.approx.f32 %0, %1;" : "=f"(y) : "f"(x));
    return y;
}

// =====================================================================
// Sequential tanh recurrence (one CTA) -- branch-free serial phase
// (R13 structure, benched 146us; only tanh swapped to MUFU).
// =====================================================================
__global__ __launch_bounds__(1024) void scan_kernel() {
    __shared__ float seps[1024];
    __shared__ float sPre[1024];
    __shared__ float sPartial[32];
    __shared__ float sDs[32][33];
    __shared__ float sInv[32];

    int t = threadIdx.x;
    int w = t >> 5;
    int lane = t & 31;

    sPre[t] = g_pre[t];   // stage pre once (off the serial chain)

    for (int b = 0; b < 32; b++) {
        int r0 = b * 32;
        // ---- parallel phase: warp w handles row r0+w ----
        const float* hrow = g_H + (size_t)(1024 + r0 + w) * 3072 + 1024;

        float hval = 0.f;
        if (lane < w) hval = hrow[r0 + lane];
        float diag = hrow[r0 + w];   // lane-uniform

        float s = 0.f;
        for (int c = lane * 4; c < r0; c += 128) {
            float4 a = *(const float4*)(hrow + c);
            float4 e = *(const float4*)(seps + c);
            s -= a.x * e.x + a.y * e.y + a.z * e.z + a.w * e.w;
        }
#pragma unroll
        for (int off = 16; off; off >>= 1) s += __shfl_xor_sync(0xffffffffu, s, off);

        float inv = 1.0f / diag;
        if (lane == 0) {
            sPartial[w] = s;
            sInv[w] = inv;
        }
        sDs[w][lane] = -hval * inv;   // zero for lane >= w
        __syncthreads();

        // ---- serial phase: warp 0, branch-free, fully unrolled ----
        if (w == 0) {
            float ds[32];
#pragma unroll
            for (int j = 0; j < 32; j++) ds[j] = sDs[lane][j];
            float acc = (sPre[r0 + lane] + sPartial[lane]) * sInv[lane];
            float tv = 0.f;
#pragma unroll
            for (int j = 0; j < 32; j++) {
                tv = tanh_mufu(acc);
                float e = __shfl_sync(0xffffffffu, tv, j);
                acc = fmaf(ds[j], e, acc);
            }
            seps[r0 + lane] = tv;
        }
        __syncthreads();
    }
    g_eps[t] = seps[t];
}

// =====================================================================
// FUSED: u (blocks 0..127) + exi (+cheb init) (blocks 128..383)
// =====================================================================
__global__ __launch_bounds__(256) void u_exi_kernel(const float* __restrict__ xi,
                                                    const float* __restrict__ w,
                                                    const float* __restrict__ C2,
                                                    const float* __restrict__ D21,
                                                    const float* __restrict__ D22,
                                                    const float* __restrict__ B2,
                                                    float inv_theta,
                                                    float* __restrict__ out) {
    __shared__ float part[8];
    int t = threadIdx.x;
    int wid = t >> 5, lane = t & 31;
    int rl = wid >> 1, half = wid & 1;

    if (blockIdx.x < 128) {
        int row = blockIdx.x * 4 + rl;
        float s = warp_dot<512>(C2 + (size_t)row * 1024 + half * 512, xi + half * 512, lane);
        s += warp_dot<512>(D21 + (size_t)row * 1024 + half * 512, g_eps + half * 512, lane);
        s += warp_dot<256>(D22 + (size_t)row * 512 + half * 256, w + half * 256, lane);
        if (lane == 0) part[wid] = s;
        __syncthreads();
        if (t < 4) out[blockIdx.x * 4 + t] = part[2 * t] + part[2 * t + 1];
    } else {
        int blk = blockIdx.x - 128;
        int row = blk * 4 + rl;
        const float* hrow = g_H + (size_t)(2048 + row) * 3072;
        float s = warp_dot<512>(hrow + half * 512, xi + half * 512, lane);
        s += warp_dot<512>(hrow + 1024 + half * 512, g_eps + half * 512, lane);
        s += warp_dot<256>(B2 + (size_t)row * 512 + half * 256, w + half * 256, lane);
        if (lane == 0) part[wid] = s;
        __syncthreads();
        if (t < 4) {
            int r = blk * 4 + t;
            float v = part[2 * t] + part[2 * t + 1];
            g_exi[r] = v;
            float x0 = v * inv_theta;
            g_x[0][r] = x0;
            g_d[0][r] = x0;
        }
    }
}

// =====================================================================
// PERSISTENT Chebyshev: all NITER_C iterations in one kernel.
// =====================================================================
__global__ __launch_bounds__(256) void cheb_persist(float* __restrict__ out,
                                                    float theta_f, float delta_f) {
    __shared__ float part[8];
    int t = threadIdx.x;
    int wid = t >> 5, lane = t & 31;
    int rl = wid >> 1, half = wid & 1;
    int row = blockIdx.x * 4 + rl;

    double theta = (double)theta_f, delta = (double)delta_f;
    double sigma = theta / delta;
    double rho_prev = 1.0 / sigma;
    int sel = 0;

    for (int k = 0; k < NITER_C; k++) {
        double rho = 1.0 / (2.0 * sigma - rho_prev);
        float c1 = (float)(rho * rho_prev);
        float c2 = (float)(2.0 * rho / delta);

        const float* xin = g_x[sel];
        float s = warp_dot<512>(g_E + (size_t)row * 1024 + half * 512, xin + half * 512, lane);
        if (lane == 0) part[wid] = s;
        __syncthreads();
        if (t < 4) {
            int r = blockIdx.x * 4 + t;
            float dot = part[2 * t] + part[2 * t + 1];
            float rres = g_exi[r] - dot;
            float dn = fmaf(c1, g_d[sel][r], c2 * rres);
            float xn = xin[r] + dn;
            g_x[sel ^ 1][r] = xn;
            g_d[sel ^ 1][r] = dn;
            if (k == NITER_C - 1) out[r] = xn;
        }
        grid_bar();
        rho_prev = rho;
        sel ^= 1;
    }
}

// =====================================================================
// host launcher
// =====================================================================
extern "C" void kernel_launch(void* const* d_in, const int* in_sizes, int n_in,
                              void* d_out, int out_size) {
    const float* w   = (const float*)d_in[1];
    const float* xi  = (const float*)d_in[2];
    const float* X   = (const float*)d_in[3];
    const float* Y   = (const float*)d_in[4];
    const float* B2  = (const float*)d_in[5];
    const float* C2  = (const float*)d_in[6];
    const float* D21 = (const float*)d_in[7];
    const float* D22 = (const float*)d_in[8];
    const float* D12 = (const float*)d_in[9];
    float* out = (float*)d_out;

    const double a_bnd = 9.5, b_bnd = 64.0;
    const double theta = 0.5 * (a_bnd + b_bnd);
    const double delta = 0.5 * (b_bnd - a_bnd);

    conv_transpose<<<dim3(96, 96), dim3(32, 8)>>>(X);

    static int smem_set = 0;
    if (!smem_set) {
        cudaFuncSetAttribute(syrk_mma, cudaFuncAttributeMaxDynamicSharedMemorySize, 2 * STAGE_BYTES);
        smem_set = 1;
    }
    syrk_mma<<<136, 256, 2 * STAGE_BYTES>>>();

    be_pre_kernel<<<784, 256>>>(Y, xi, w, D12);
    scan_kernel<<<1, 1024>>>();
    u_exi_kernel<<<384, 256>>>(xi, w, C2, D21, D22, B2, (float)(1.0 / theta), out);
    cheb_persist<<<256, 256>>>(out + 512, (float)theta, (float)delta);
}